// round 17
// baseline (speedup 1.0000x reference)
#include <cuda_runtime.h>
#include <math.h>
#include <stdint.h>

#define NT      128            // warps 0,1 = LSTM chain; warps 2,3 = helpers
#define EPB     64             // batch elements per block (1 per chain thread)
#define NB      1024           // 65536 / EPB
#define TSTEPS  128
#define TT      8              // timesteps per tile
#define NTILES  16             // TSTEPS / TT
#define NSTAGE  2              // per-helper-warp cp.async ring depth
#define ROW4    7              // float4s per smem row (6 data + 1 pad) -> conflict-free LDS.128
#define WROWS   32             // elements per warp-pair
#define WTILE4  (WROWS * ROW4) // 224 float4 per ring stage
#define NPAIRS  (TSTEPS / 2)   // 64 time-pairs (4 per tile)

typedef unsigned long long u64;

static __device__ float g_partial[NB];
static __device__ unsigned int g_count = 0;

__device__ __forceinline__ float tanha(float x) {
    float y; asm("tanh.approx.f32 %0, %1;" : "=f"(y) : "f"(x)); return y;
}
__device__ __forceinline__ u64 pk(float lo, float hi) {
    u64 d; asm("mov.b64 %0, {%1, %2};" : "=l"(d) : "f"(lo), "f"(hi)); return d;
}
__device__ __forceinline__ void upk(float& lo, float& hi, u64 v) {
    asm("mov.b64 {%0, %1}, %2;" : "=f"(lo), "=f"(hi) : "l"(v));
}
__device__ __forceinline__ u64 fma2(u64 a, u64 b, u64 c) {
    u64 d; asm("fma.rn.f32x2 %0, %1, %2, %3;" : "=l"(d) : "l"(a), "l"(b), "l"(c)); return d;
}
__device__ __forceinline__ void cp_async16(uint32_t dst, const float4* src) {
    asm volatile("cp.async.cg.shared.global [%0], [%1], 16;" :: "r"(dst), "l"(src));
}
#define PBAR(id) asm volatile("bar.sync %0, %1;" :: "r"(id), "r"(64) : "memory")

__global__ __launch_bounds__(NT, 5)
void recdyn_kernel(const float* __restrict__ hist,   // (B,1,T,3)
                   const float* __restrict__ h0,
                   const float* __restrict__ c0,
                   const float* __restrict__ target,
                   const float* __restrict__ Wih,    // (4,3)
                   const float* __restrict__ Whh,    // (4,1)
                   const float* __restrict__ bih,
                   const float* __restrict__ bhh,
                   const float* __restrict__ Wm,     // (3,128)
                   const float* __restrict__ bm,
                   const float* __restrict__ Wv,     // (6,128)
                   const float* __restrict__ bv,
                   float* __restrict__ out)
{
    // head weights, PRE-HALVED (absorb h2=2h), time-pair interleaved (as R16)
    __shared__ __align__(16) u64 sw2[NPAIRS * 8];
    __shared__ __align__(16) u64 sw8p[NPAIRS];
    // x rings: one per helper warp
    __shared__ __align__(16) float sbuf[2 * NSTAGE * WTILE4 * 4];
    // xp handoff: [pair][buf][step 0..7][lane] float4 (i,f,g,o projections incl. bias)
    __shared__ __align__(16) float4 xpb[2 * 2 * TT * 32];
    // h handoff: [pair][buf][steppair 0..3][lane] u64 = (h2 even, h2 odd)
    __shared__ __align__(16) u64 hb[2 * 2 * 4 * 32];
    __shared__ float sred[NT];
    __shared__ int slast;

    const int tid  = threadIdx.x;
    const int lane = tid & 31;
    const int wid  = tid >> 5;

    // ---- stage head weights (all threads) ----
    for (int i = tid; i < NPAIRS * 8; i += NT) {
        int p = i >> 3, j = i & 7;
        int t0 = 2 * p;
        float w0, w1;
        if (j < 3) { w0 = Wm[j * TSTEPS + t0]; w1 = Wm[j * TSTEPS + t0 + 1]; }
        else       { w0 = Wv[(j - 3) * TSTEPS + t0]; w1 = Wv[(j - 3) * TSTEPS + t0 + 1]; }
        reinterpret_cast<float2*>(sw2)[i] = make_float2(0.5f * w0, 0.5f * w1);
    }
    for (int p = tid; p < NPAIRS; p += NT) {
        int t0 = 2 * p;
        reinterpret_cast<float2*>(sw8p)[p] =
            make_float2(0.5f * Wv[5 * TSTEPS + t0], 0.5f * Wv[5 * TSTEPS + t0 + 1]);
    }
    __syncthreads();

    float val = 0.0f;

    if (wid < 2) {
        // ================= CHAIN WARPS =================
        const int pairid = wid;
        const int barid  = 1 + pairid;
        const int b      = blockIdx.x * EPB + pairid * 32 + lane;

        float wh[4];
        #pragma unroll
        for (int k = 0; k < 4; ++k) {
            float s = (k == 2) ? 1.0f : 0.5f;
            wh[k] = 0.5f * s * Whh[k];    // extra 0.5 absorbs h2 = 2h
        }
        float h2 = 2.0f * h0[b];
        float c  = c0[b];

        PBAR(barid);                       // r0: xp(0) published by helper
        for (int g = 0; g < NTILES; ++g) {
            const float4* xp4 = xpb + (size_t)(pairid * 2 + (g & 1)) * TT * 32 + lane;
            u64* hrow = hb + (size_t)(pairid * 2 + (g & 1)) * 4 * 32 + lane;
            #pragma unroll
            for (int pp = 0; pp < 4; ++pp) {
                float4 xA = xp4[(pp * 2 + 0) * 32];
                float gi = fmaf(h2, wh[0], xA.x);
                float gf = fmaf(h2, wh[1], xA.y);
                float gg = fmaf(h2, wh[2], xA.z);
                float go = fmaf(h2, wh[3], xA.w);
                float si = fmaf(tanha(gi), 0.5f, 0.5f);
                float sf = fmaf(tanha(gf), 0.5f, 0.5f);
                float tg = tanha(gg);
                float to_ = tanha(go);
                c = fmaf(sf, c, si * tg);
                float tc = tanha(c);
                h2 = fmaf(to_, tc, tc);
                float h2a = h2;

                float4 xB = xp4[(pp * 2 + 1) * 32];
                gi = fmaf(h2, wh[0], xB.x);
                gf = fmaf(h2, wh[1], xB.y);
                gg = fmaf(h2, wh[2], xB.z);
                go = fmaf(h2, wh[3], xB.w);
                si = fmaf(tanha(gi), 0.5f, 0.5f);
                sf = fmaf(tanha(gf), 0.5f, 0.5f);
                tg = tanha(gg);
                to_ = tanha(go);
                c = fmaf(sf, c, si * tg);
                tc = tanha(c);
                h2 = fmaf(to_, tc, tc);

                hrow[pp * 32] = pk(h2a, h2);
            }
            PBAR(barid);                   // r_{g+1}: h(g) published
        }
    } else {
        // ================= HELPER WARPS =================
        const int pairid = wid - 2;
        const int barid  = 1 + pairid;
        const int b      = blockIdx.x * EPB + pairid * 32 + lane;

        // ---- cp.async ring: 192 f4 slots/tile, 6 per lane ----
        const int seg0 = lane / 6;
        const int q0   = lane - seg0 * 6;
        const float4* gwarp = reinterpret_cast<const float4*>(hist)
                            + ((size_t)blockIdx.x * EPB + pairid * 32) * 96;
        float* wbase = sbuf + (size_t)pairid * (NSTAGE * WTILE4 * 4);
        const uint32_t wbase_u32 = (uint32_t)__cvta_generic_to_shared(wbase);

        #pragma unroll
        for (int pg = 0; pg < 2; ++pg) {
            const float4* src = gwarp + pg * 6;
            uint32_t dstb = wbase_u32 + (uint32_t)(pg * WTILE4) * 16u;
            int s = seg0, qq = q0;
            #pragma unroll
            for (int k = 0; k < 6; ++k) {
                cp_async16(dstb + (uint32_t)(s * ROW4 + qq) * 16u,
                           src + (size_t)s * 96 + qq);
                s += 5; qq += 2; if (qq >= 6) { qq -= 6; ++s; }
            }
            asm volatile("cp.async.commit_group;");
        }

        // ---- rotation basis + target rotation + folded weights ----
        const float4* xr = reinterpret_cast<const float4*>(hist + (size_t)b * (TSTEPS * 3));
        float4 r93 = xr[93];
        float4 r94 = xr[94];
        float4 r95 = xr[95];

        float v1x = r95.y, v1y = r95.z, v1z = r95.w;
        float v2x = r94.z, v2y = r94.w, v2z = r95.x;
        float v3x = r93.w, v3y = r94.x, v3z = r94.y;

        float n1 = rsqrtf(v1x*v1x + v1y*v1y + v1z*v1z);
        float b1x = v1x*n1, b1y = v1y*n1, b1z = v1z*n1;

        float p  = v2x*b1x + v2y*b1y + v2z*b1z;
        float a2x = v2x - p*b1x, a2y = v2y - p*b1y, a2z = v2z - p*b1z;
        float n2 = rsqrtf(a2x*a2x + a2y*a2y + a2z*a2z);
        float b2x = a2x*n2, b2y = a2y*n2, b2z = a2z*n2;

        float b3x = b1y*b2z - b1z*b2y;
        float b3y = b1z*b2x - b1x*b2z;
        float b3z = b1x*b2y - b1y*b2x;

        float sgn = (v3x*b3x + v3y*b3y + v3z*b3z) > 0.0f ? 1.0f : -1.0f;
        float c3x = sgn*b3x, c3y = sgn*b3y, c3z = sgn*b3z;

        float tx = target[b*3+0], ty = target[b*3+1], tz = target[b*3+2];
        const float rt0 = tx*b1x + ty*b1y + tz*b1z;
        const float rt1 = tx*b2x + ty*b2y + tz*b2z;
        const float rt2 = tx*c3x + ty*c3y + tz*c3z;

        float wihr[12];
        #pragma unroll
        for (int k = 0; k < 12; ++k) wihr[k] = Wih[k];

        float wp[4][3], bbs[4];
        #pragma unroll
        for (int k = 0; k < 4; ++k) {
            float s = (k == 2) ? 1.0f : 0.5f;
            wp[k][0] = s * (wihr[k*3+0]*b1x + wihr[k*3+1]*b2x + wihr[k*3+2]*c3x);
            wp[k][1] = s * (wihr[k*3+0]*b1y + wihr[k*3+1]*b2y + wihr[k*3+2]*c3y);
            wp[k][2] = s * (wihr[k*3+0]*b1z + wihr[k*3+1]*b2z + wihr[k*3+2]*c3z);
            bbs[k] = s * (bih[k] + bhh[k]);
        }

        // ---- xp producer lambda-ish macro via inline loop ----
        // compute xp for tile t from ring[t&1] into xpb[pair][t&1]
        u64 acc[9];
        #pragma unroll
        for (int j = 0; j < 9; ++j) acc[j] = pk(0.f, 0.f);

        // prologue: xp(0)
        asm volatile("cp.async.wait_group 1;");
        {
            const int t = 0;
            const float4* brow = reinterpret_cast<const float4*>(wbase)
                               + (t & 1) * WTILE4 + lane * ROW4;
            float4* xo = xpb + (size_t)(pairid * 2 + (t & 1)) * TT * 32 + lane;
            #pragma unroll
            for (int half = 0; half < 2; ++half) {
                float4 p0 = brow[half*3+0], p1 = brow[half*3+1], p2 = brow[half*3+2];
                float xs[12] = {p0.x,p0.y,p0.z,p0.w, p1.x,p1.y,p1.z,p1.w, p2.x,p2.y,p2.z,p2.w};
                #pragma unroll
                for (int k = 0; k < 4; ++k) {
                    float x0 = xs[3*k+0], x1 = xs[3*k+1], x2 = xs[3*k+2];
                    float e0 = fmaf(x0, wp[0][0], fmaf(x1, wp[0][1], fmaf(x2, wp[0][2], bbs[0])));
                    float e1 = fmaf(x0, wp[1][0], fmaf(x1, wp[1][1], fmaf(x2, wp[1][2], bbs[1])));
                    float e2 = fmaf(x0, wp[2][0], fmaf(x1, wp[2][1], fmaf(x2, wp[2][2], bbs[2])));
                    float e3 = fmaf(x0, wp[3][0], fmaf(x1, wp[3][1], fmaf(x2, wp[3][2], bbs[3])));
                    xo[(half*4+k) * 32] = make_float4(e0, e1, e2, e3);
                }
            }
        }
        PBAR(barid);                       // r0: xp(0) ready

        for (int g = 0; g < NTILES; ++g) {
            if (g < NTILES - 1) {
                const int t = g + 1;
                if (t + 1 < NTILES) {
                    const float4* src = gwarp + (t + 1) * 6;
                    uint32_t dstb = wbase_u32 + (uint32_t)(((t + 1) & 1) * WTILE4) * 16u;
                    int s = seg0, qq = q0;
                    #pragma unroll
                    for (int k = 0; k < 6; ++k) {
                        cp_async16(dstb + (uint32_t)(s * ROW4 + qq) * 16u,
                                   src + (size_t)s * 96 + qq);
                        s += 5; qq += 2; if (qq >= 6) { qq -= 6; ++s; }
                    }
                    asm volatile("cp.async.commit_group;");
                    asm volatile("cp.async.wait_group 1;");
                } else {
                    asm volatile("cp.async.wait_group 0;");
                }
                const float4* brow = reinterpret_cast<const float4*>(wbase)
                                   + (t & 1) * WTILE4 + lane * ROW4;
                float4* xo = xpb + (size_t)(pairid * 2 + (t & 1)) * TT * 32 + lane;
                #pragma unroll
                for (int half = 0; half < 2; ++half) {
                    float4 p0 = brow[half*3+0], p1 = brow[half*3+1], p2 = brow[half*3+2];
                    float xs[12] = {p0.x,p0.y,p0.z,p0.w, p1.x,p1.y,p1.z,p1.w, p2.x,p2.y,p2.z,p2.w};
                    #pragma unroll
                    for (int k = 0; k < 4; ++k) {
                        float x0 = xs[3*k+0], x1 = xs[3*k+1], x2 = xs[3*k+2];
                        float e0 = fmaf(x0, wp[0][0], fmaf(x1, wp[0][1], fmaf(x2, wp[0][2], bbs[0])));
                        float e1 = fmaf(x0, wp[1][0], fmaf(x1, wp[1][1], fmaf(x2, wp[1][2], bbs[1])));
                        float e2 = fmaf(x0, wp[2][0], fmaf(x1, wp[2][1], fmaf(x2, wp[2][2], bbs[2])));
                        float e3 = fmaf(x0, wp[3][0], fmaf(x1, wp[3][1], fmaf(x2, wp[3][2], bbs[3])));
                        xo[(half*4+k) * 32] = make_float4(e0, e1, e2, e3);
                    }
                }
            }
            PBAR(barid);                   // r_{g+1}: xp(g+1) published, h(g) ready

            // ---- head accumulation for tile g (1-tile lag) ----
            const u64* hrow = hb + (size_t)(pairid * 2 + (g & 1)) * 4 * 32 + lane;
            const ulonglong2* w8q2 = reinterpret_cast<const ulonglong2*>(sw8p + g * 4);
            ulonglong2 w8a = w8q2[0];
            ulonglong2 w8b = w8q2[1];
            #pragma unroll
            for (int pp = 0; pp < 4; ++pp) {
                u64 Hp = hrow[pp * 32];
                const ulonglong2* wr = reinterpret_cast<const ulonglong2*>(sw2 + (g * 4 + pp) * 8);
                ulonglong2 q0v = wr[0];
                ulonglong2 q1v = wr[1];
                ulonglong2 q2v = wr[2];
                ulonglong2 q3v = wr[3];
                u64 w8v = (pp == 0) ? w8a.x : (pp == 1) ? w8a.y : (pp == 2) ? w8b.x : w8b.y;

                acc[0] = fma2(Hp, q0v.x, acc[0]);
                acc[1] = fma2(Hp, q0v.y, acc[1]);
                acc[2] = fma2(Hp, q1v.x, acc[2]);
                acc[3] = fma2(Hp, q1v.y, acc[3]);
                acc[4] = fma2(Hp, q2v.x, acc[4]);
                acc[5] = fma2(Hp, q2v.y, acc[5]);
                acc[6] = fma2(Hp, q3v.x, acc[6]);
                acc[7] = fma2(Hp, q3v.y, acc[7]);
                acc[8] = fma2(Hp, w8v,   acc[8]);
            }
        }

        // ---- NLL epilogue ----
        float hv[9];
        #pragma unroll
        for (int j = 0; j < 9; ++j) {
            float lo, hi; upk(lo, hi, acc[j]);
            hv[j] = lo + hi;
        }
        float m0 = hv[0] + bm[0], m1 = hv[1] + bm[1], m2 = hv[2] + bm[2];
        float e0 = hv[3] + bv[0], e1 = hv[4] + bv[1], e2 = hv[5] + bv[2];
        float e3 = hv[6] + bv[3], e4 = hv[7] + bv[4], e5 = hv[8] + bv[5];

        float d0 = m0 - rt0, d1 = m1 - rt1, d2 = m2 - rt2;
        float z0 = d0;
        float z1 = d1 - e0 * z0;
        float z2 = d2 - e1 * z0 - e2 * z1;

        float quad = z0*z0*__expf(-e3) + z1*z1*__expf(-e4) + z2*z2*__expf(-e5);
        val = 0.5f * (__expf(e3) + __expf(e4) + __expf(e5) + quad);
    }

    // ---- block tree reduction (deterministic; chain threads contribute 0) ----
    sred[tid] = val;
    __syncthreads();
    #pragma unroll
    for (int off = NT/2; off > 0; off >>= 1) {
        if (tid < off) sred[tid] += sred[tid + off];
        __syncthreads();
    }

    // ---- last-block grid reduction (deterministic fixed order) ----
    if (tid == 0) {
        g_partial[blockIdx.x] = sred[0];
        __threadfence();
        unsigned int n = atomicAdd(&g_count, 1u);
        slast = (n == NB - 1) ? 1 : 0;
    }
    __syncthreads();

    if (slast) {
        float s = 0.0f;
        #pragma unroll
        for (int k = 0; k < NB / NT; ++k)
            s += __ldcg(&g_partial[tid * (NB / NT) + k]);
        sred[tid] = s;
        __syncthreads();
        #pragma unroll
        for (int off = NT/2; off > 0; off >>= 1) {
            if (tid < off) sred[tid] += sred[tid + off];
            __syncthreads();
        }
        if (tid == 0) {
            out[0] = sred[0] * (1.0f / 65536.0f);
            g_count = 0;   // reset for next graph replay
        }
    }
}

extern "C" void kernel_launch(void* const* d_in, const int* in_sizes, int n_in,
                              void* d_out, int out_size)
{
    const float* hist   = (const float*)d_in[0];
    const float* h0     = (const float*)d_in[1];
    const float* c0     = (const float*)d_in[2];
    const float* target = (const float*)d_in[3];
    const float* Wih    = (const float*)d_in[4];
    const float* Whh    = (const float*)d_in[5];
    const float* bih    = (const float*)d_in[6];
    const float* bhh    = (const float*)d_in[7];
    const float* Wm     = (const float*)d_in[8];
    const float* bm     = (const float*)d_in[9];
    const float* Wv     = (const float*)d_in[10];
    const float* bv     = (const float*)d_in[11];

    recdyn_kernel<<<NB, NT>>>(hist, h0, c0, target,
                              Wih, Whh, bih, bhh, Wm, bm, Wv, bv,
                              (float*)d_out);
}